// round 7
// baseline (speedup 1.0000x reference)
#include <cuda_runtime.h>
#include <math.h>

#define D 256
#define S 2048
#define BATCH 32
#define V 1024
#define NROWS (BATCH * S)   // 65536
#define BR 64               // rows (s) per block
#define BC 128              // codes per chunk
#define NT 256              // threads per block
#define ET_STRIDE 132       // padded code stride (float4-aligned)
#define EQ_STRIDE 260       // epilogue z_q staging stride

__device__ int    g_counts[V];
__device__ double g_loss;
__device__ float  g_enorm[V];

// ---------------------------------------------------------------------------
// Emulate XLA GPU row-reduction (row=256 f32, vec x2, warp-per-row):
// lane l accumulates elems (2l,2l+1,2l+64,2l+65,...) with separate RN mul/add,
// then shfl_down tree offsets 16,8,4,2,1; result = lane 0.
// ---------------------------------------------------------------------------
template <typename F>
__device__ __forceinline__ float xla_rowsum_sq(F vals) {
    float p[32];
#pragma unroll
    for (int l = 0; l < 32; ++l) {
        float acc = 0.f;
#pragma unroll
        for (int j = 0; j < 4; ++j) {
            int d0 = 2 * l + 64 * j;
            float x = vals(d0);
            acc = __fadd_rn(acc, __fmul_rn(x, x));
            float y = vals(d0 + 1);
            acc = __fadd_rn(acc, __fmul_rn(y, y));
        }
        p[l] = acc;
    }
#pragma unroll
    for (int off = 16; off > 0; off >>= 1)
#pragma unroll
        for (int l = 0; l < 16; ++l)
            if (l < off) p[l] = __fadd_rn(p[l], p[l + off]);
    return p[0];
}

// ---------------------------------------------------------------------------
// init: per-code squared norms (XLA reduce order), zero counters
// 32 blocks x 32 threads — was 1 block (131us on one SM)
// ---------------------------------------------------------------------------
__global__ void vq_init(const float* __restrict__ emb) {
    int c = blockIdx.x * 32 + threadIdx.x;   // 1024 codes
    const float* e = emb + (size_t)c * D;
    g_enorm[c] = xla_rowsum_sq([&](int k) { return e[k]; });
    g_counts[c] = 0;
    if (c == 0) g_loss = 0.0;
}

// ---------------------------------------------------------------------------
// main: fused fp32 distance-GEMM + argmin + one-hot + z_q + loss
// one block = 64 consecutive s positions within one batch b
// register tile 4 rows x 8 codes (32 FFMA per 3 LDS.128 -> FFMA-bound)
// ---------------------------------------------------------------------------
__global__ __launch_bounds__(NT, 1) void vq_main(
    const float* __restrict__ z, const float* __restrict__ emb,
    float* __restrict__ p_zq, float* __restrict__ p_oh, float* __restrict__ p_idx)
{
    extern __shared__ float sm[];
    float* zs   = sm;                    // [256][64]  z tile (full precision)
    float* et   = zs + D * BR;           // [256][132] emb chunk / scratch / z_q staging
    float* arow = et + D * ET_STRIDE;    // [64]  row norms (XLA-order)
    float* brow = arow + BR;             // [128] code norms for chunk
    int*   sidx = (int*)(brow + BC);     // [64]  winning indices

    const int tid = threadIdx.x;
    const int bid = blockIdx.x;
    const int b   = bid >> 5;            // 32 s-chunks per batch
    const int s0  = (bid & 31) << 6;
    const size_t n0 = (size_t)b * S + s0;

    // zero this block's one-hot rows (p_oh is 8-byte aligned -> float2)
    if (p_oh) {
        float2* oh2 = (float2*)(p_oh + n0 * V);
        float2 zz = make_float2(0.f, 0.f);
        for (int i = tid; i < (BR * V) / 2; i += NT) oh2[i] = zz;
    }

    // load z tile: z[b][d][s0..s0+63] — contiguous in s, float4 coalesced
    const float* zb = z + ((size_t)b * D * S) + s0;
    for (int i = tid; i < (D * BR) / 4; i += NT) {
        int d = i >> 4, sv = i & 15;
        float4 v = *(const float4*)(zb + (size_t)d * S + (sv << 2));
        *(float4*)(zs + d * BR + (sv << 2)) = v;
    }
    __syncthreads();

    // row squared norms — bit-exact XLA reduce emulation, one thread per row
    if (tid < BR) {
        int s = tid;
        arow[s] = xla_rowsum_sq([&](int k) { return zs[k * BR + s]; });
    }
    __syncthreads();

    const int tx = tid & 15;   // s-group (4 rows each)
    const int ty = tid >> 4;   // c-group (8 codes each)
    float rmin[4] = {3.4e38f, 3.4e38f, 3.4e38f, 3.4e38f};
    int   ridx[4] = {0, 0, 0, 0};
    const float4* embF4 = (const float4*)emb;

    for (int c0 = 0; c0 < V; c0 += BC) {
        __syncthreads();
        // transpose-load emb chunk into et[d][c]
        for (int i = tid; i < BC * (D / 4); i += NT) {
            int c = i & (BC - 1), d4 = i >> 7;
            float4 v = embF4[(size_t)(c0 + c) * (D / 4) + d4];
            int dbase = d4 << 2;
            et[(dbase + 0) * ET_STRIDE + c] = v.x;
            et[(dbase + 1) * ET_STRIDE + c] = v.y;
            et[(dbase + 2) * ET_STRIDE + c] = v.z;
            et[(dbase + 3) * ET_STRIDE + c] = v.w;
        }
        if (tid < BC) brow[tid] = g_enorm[c0 + tid];
        __syncthreads();

        float acc[4][8];
#pragma unroll
        for (int j = 0; j < 4; ++j)
#pragma unroll
            for (int k = 0; k < 8; ++k) acc[j][k] = 0.f;

        // sequential FFMA chain over d ascending (cuBLAS sgemm accumulation)
        const float* zp = zs + (tx << 2);
        const float* ep = et + (ty << 3);
#pragma unroll 4
        for (int d = 0; d < D; ++d) {
            float4 a  = *(const float4*)(zp + (size_t)d * BR);
            float4 b0 = *(const float4*)(ep + (size_t)d * ET_STRIDE);
            float4 b1 = *(const float4*)(ep + (size_t)d * ET_STRIDE + 4);
            float av[4] = {a.x, a.y, a.z, a.w};
            float bv[8] = {b0.x, b0.y, b0.z, b0.w, b1.x, b1.y, b1.z, b1.w};
#pragma unroll
            for (int j = 0; j < 4; ++j)
#pragma unroll
                for (int k = 0; k < 8; ++k)
                    acc[j][k] += av[j] * bv[k];
        }

        // reference-matching distance: fl(fl(a + b) - 2*c); 2c exact
#pragma unroll
        for (int j = 0; j < 4; ++j) {
            float as = arow[(tx << 2) + j];
#pragma unroll
            for (int k = 0; k < 8; ++k) {
                int c = (ty << 3) + k;
                float t1   = __fadd_rn(as, brow[c]);
                float dist = __fadd_rn(t1, -2.0f * acc[j][k]);
                if (dist < rmin[j]) { rmin[j] = dist; ridx[j] = c0 + c; }  // c ascending => ties keep lowest
            }
        }
    }
    __syncthreads();

    // cross-thread argmin reduction per row — LEXICOGRAPHIC (value, index)
    float* redv = et;
    int*   redi = (int*)(et + 16 * 64);
#pragma unroll
    for (int j = 0; j < 4; ++j) {
        redv[ty * 64 + (tx << 2) + j] = rmin[j];
        redi[ty * 64 + (tx << 2) + j] = ridx[j];
    }
    __syncthreads();
    if (tid < BR) {
        int s = tid;
        float bv = redv[s]; int bi = redi[s];
#pragma unroll
        for (int t = 1; t < 16; ++t) {
            float v  = redv[t * 64 + s];
            int   ii = redi[t * 64 + s];
            if (v < bv || (v == bv && ii < bi)) { bv = v; bi = ii; }   // ties -> lowest code index (jnp.argmin)
        }
        sidx[s] = bi;
        if (p_idx) p_idx[n0 + s] = (float)bi;
        if (p_oh)  p_oh[(n0 + s) * (size_t)V + bi] = 1.0f;
        atomicAdd(&g_counts[bi], 1);
    }
    __syncthreads();

    // stage z_q rows (exact emb gather — onehot@emb FFMA chain is exact)
    float* eq = et;   // [64][EQ_STRIDE]
    for (int i = tid; i < BR * (D / 4); i += NT) {
        int s = i >> 6, d4 = i & 63;                       // coalesced emb row read
        float4 v = embF4[(size_t)sidx[s] * (D / 4) + d4];
        float* p = eq + s * EQ_STRIDE + (d4 << 2);
        p[0] = v.x; p[1] = v.y; p[2] = v.z; p[3] = v.w;
    }
    __syncthreads();

    // loss partial: (z_q - zp)^2
    float lp = 0.f;
    for (int i = tid; i < BR * D; i += NT) {
        int d = i >> 6, s = i & 63;
        float diff = __fadd_rn(eq[s * EQ_STRIDE + d], -zs[d * BR + s]);
        lp += diff * diff;
    }

    // z_q_st output: fl(zp + fl(z_q - zp)) — reference straight-through rounding.
    // SCALAR stores (p_zq = out+1 is only 4-byte aligned).
    if (p_zq) {
        for (int i = tid; i < BR * D; i += NT) {
            int s = i >> 8, d = i & 255;                   // consecutive tid -> consecutive d: coalesced
            float zpv = zs[d * BR + s];
            float st  = __fadd_rn(zpv, __fadd_rn(eq[s * EQ_STRIDE + d], -zpv));
            p_zq[(n0 + s) * (size_t)D + d] = st;
        }
    }

    // block loss reduction (reuse zs — all zs reads done)
    __syncthreads();
    zs[tid] = lp;
    __syncthreads();
    for (int st = NT / 2; st > 0; st >>= 1) {
        if (tid < st) zs[tid] += zs[tid + st];
        __syncthreads();
    }
    if (tid == 0) atomicAdd(&g_loss, (double)zs[0]);
}

// ---------------------------------------------------------------------------
// final: perplexity from counts, loss scalar
// ---------------------------------------------------------------------------
__global__ void vq_final(float* p_loss, float* p_ppl) {
    __shared__ float red[V];
    int c = threadIdx.x;
    float e = (float)g_counts[c] * (1.0f / 65536.0f);
    red[c] = e * logf(e + 1e-10f);
    __syncthreads();
    for (int st = 512; st > 0; st >>= 1) { if (c < st) red[c] += red[c + st]; __syncthreads(); }
    if (c == 0) {
        if (p_ppl)  *p_ppl  = expf(-red[0]);
        if (p_loss) *p_loss = (float)(1.25 * g_loss * (1.0 / 16777216.0));
    }
}

extern "C" void kernel_launch(void* const* d_in, const int* in_sizes, int n_in,
                              void* d_out, int out_size) {
    const float* z   = (const float*)d_in[0];
    const float* emb = (const float*)d_in[1];
    if (n_in >= 2 && in_sizes[0] == V * D && in_sizes[1] == NROWS * D) {
        z   = (const float*)d_in[1];
        emb = (const float*)d_in[0];
    }

    float* out = (float*)d_out;
    float *p_loss = nullptr, *p_zq = nullptr, *p_ppl = nullptr, *p_oh = nullptr, *p_idx = nullptr;
    const long long ZQ = (long long)NROWS * D;     // 16777216
    const long long OH = (long long)NROWS * V;     // 67108864
    const long long TOTAL = 1 + ZQ + 1 + OH + NROWS;  // 83951618
    long long osz = (long long)out_size;

    if (osz >= TOTAL) {                       // full 5-tuple concat
        p_loss = out;
        p_zq   = out + 1;
        p_ppl  = out + 1 + ZQ;
        p_oh   = p_ppl + 1;
        p_idx  = p_oh + OH;
    } else if (osz == ZQ)        p_zq  = out;
    else if (osz == OH)          p_oh  = out;
    else if (osz == NROWS)       p_idx = out;
    else if (osz == 1)           p_loss = out;
    else if (osz == 2)           { p_loss = out; p_ppl = out + 1; }
    else if (osz == ZQ + 1)      { p_loss = out; p_zq = out + 1; }
    else if (osz == ZQ + 2)      { p_loss = out; p_zq = out + 1; p_ppl = out + 1 + ZQ; }

    size_t smem = (size_t)(D * BR + D * ET_STRIDE + BR + BC) * sizeof(float) + BR * sizeof(int);
    cudaFuncSetAttribute(vq_main, cudaFuncAttributeMaxDynamicSharedMemorySize, (int)smem);

    vq_init<<<32, 32>>>(emb);
    vq_main<<<NROWS / BR, NT, smem>>>(z, emb, p_zq, p_oh, p_idx);
    vq_final<<<1, V>>>(p_loss, p_ppl);
}

// round 8
// speedup vs baseline: 1.5609x; 1.5609x over previous
#include <cuda_runtime.h>
#include <math.h>

#define D 256
#define S 2048
#define BATCH 32
#define V 1024
#define NROWS (BATCH * S)   // 65536
#define BR 128              // rows (s) per block
#define BC 64               // codes per chunk
#define NT 512              // threads per block
#define ET_STRIDE 68        // padded code stride (float4-aligned, conflict-free)

__device__ int    g_counts[V];
__device__ double g_loss;
__device__ float  g_enorm[V];

// ---------------------------------------------------------------------------
// Emulate XLA GPU row-reduction (row=256 f32, vec x2, warp-per-row):
// lane l accumulates elems (2l,2l+1,2l+64,2l+65,...) with separate RN mul/add,
// then shfl_down tree offsets 16,8,4,2,1; result = lane 0.
// ---------------------------------------------------------------------------
template <typename F>
__device__ __forceinline__ float xla_rowsum_sq(F vals) {
    float p[32];
#pragma unroll
    for (int l = 0; l < 32; ++l) {
        float acc = 0.f;
#pragma unroll
        for (int j = 0; j < 4; ++j) {
            int d0 = 2 * l + 64 * j;
            float x = vals(d0);
            acc = __fadd_rn(acc, __fmul_rn(x, x));
            float y = vals(d0 + 1);
            acc = __fadd_rn(acc, __fmul_rn(y, y));
        }
        p[l] = acc;
    }
#pragma unroll
    for (int off = 16; off > 0; off >>= 1)
#pragma unroll
        for (int l = 0; l < 16; ++l)
            if (l < off) p[l] = __fadd_rn(p[l], p[l + off]);
    return p[0];
}

// ---------------------------------------------------------------------------
// init: per-code squared norms (XLA reduce order), zero counters
// ---------------------------------------------------------------------------
__global__ void vq_init(const float* __restrict__ emb) {
    int c = blockIdx.x * 32 + threadIdx.x;   // 1024 codes
    const float* e = emb + (size_t)c * D;
    g_enorm[c] = xla_rowsum_sq([&](int k) { return e[k]; });
    g_counts[c] = 0;
    if (c == 0) g_loss = 0.0;
}

// ---------------------------------------------------------------------------
// main: fused fp32 distance-GEMM + argmin + one-hot + z_q + loss
// one block = 128 consecutive s positions within one batch b; NT=512
// micro-tile 4 rows x 4 codes; tx spans full warp -> conflict-free a-loads,
// ty warp-uniform -> broadcast b-loads; 4 warps/SMSP hides LDS latency
// ---------------------------------------------------------------------------
__global__ __launch_bounds__(NT, 1) void vq_main(
    const float* __restrict__ z, const float* __restrict__ emb,
    float* __restrict__ p_zq, float* __restrict__ p_oh, float* __restrict__ p_idx)
{
    extern __shared__ float sm[];
    float* zs   = sm;                    // [256][128] z tile (full precision)
    float* et   = zs + D * BR;           // [256][68]  emb chunk / argmin scratch
    float* arow = et + D * ET_STRIDE;    // [128] row norms (XLA-order)
    float* brow = arow + BR;             // [64]  code norms for chunk
    int*   sidx = (int*)(brow + BC);     // [128] winning indices

    const int tid = threadIdx.x;
    const int bid = blockIdx.x;
    const int b   = bid >> 4;            // 16 s-chunks per batch
    const int s0  = (bid & 15) << 7;
    const size_t n0 = (size_t)b * S + s0;

    // zero this block's one-hot rows (p_oh is 8-byte aligned -> float2)
    if (p_oh) {
        float2* oh2 = (float2*)(p_oh + n0 * V);
        float2 zz = make_float2(0.f, 0.f);
        for (int i = tid; i < (BR * V) / 2; i += NT) oh2[i] = zz;
    }

    // load z tile: z[b][d][s0..s0+127] — contiguous in s, float4 coalesced
    const float* zb = z + ((size_t)b * D * S) + s0;
    for (int i = tid; i < (D * BR) / 4; i += NT) {
        int d = i >> 5, sv = i & 31;
        float4 v = *(const float4*)(zb + (size_t)d * S + (sv << 2));
        *(float4*)(zs + d * BR + (sv << 2)) = v;
    }
    __syncthreads();

    // row squared norms — bit-exact XLA reduce emulation, one thread per row
    if (tid < BR) {
        int s = tid;
        arow[s] = xla_rowsum_sq([&](int k) { return zs[k * BR + s]; });
    }
    __syncthreads();

    const int tx = tid & 31;   // s-group (4 rows each) — spans the warp
    const int ty = tid >> 5;   // c-group (4 codes each) — warp-uniform
    float rmin[4] = {3.4e38f, 3.4e38f, 3.4e38f, 3.4e38f};
    int   ridx[4] = {0, 0, 0, 0};
    const float4* embF4 = (const float4*)emb;

    for (int c0 = 0; c0 < V; c0 += BC) {
        __syncthreads();
        // transpose-load emb chunk into et[d][c]
        for (int i = tid; i < BC * (D / 4); i += NT) {
            int c = i & 63, d4 = i >> 6;
            float4 v = embF4[(size_t)(c0 + c) * (D / 4) + d4];
            int dbase = d4 << 2;
            et[(dbase + 0) * ET_STRIDE + c] = v.x;
            et[(dbase + 1) * ET_STRIDE + c] = v.y;
            et[(dbase + 2) * ET_STRIDE + c] = v.z;
            et[(dbase + 3) * ET_STRIDE + c] = v.w;
        }
        if (tid < BC) brow[tid] = g_enorm[c0 + tid];
        __syncthreads();

        float acc[4][4];
#pragma unroll
        for (int j = 0; j < 4; ++j)
#pragma unroll
            for (int k = 0; k < 4; ++k) acc[j][k] = 0.f;

        // sequential FFMA chain over d ascending (cuBLAS sgemm accumulation)
        const float* zp = zs + (tx << 2);
        const float* ep = et + (ty << 2);
#pragma unroll 4
        for (int d = 0; d < D; ++d) {
            float4 a  = *(const float4*)(zp + (size_t)d * BR);
            float4 bb = *(const float4*)(ep + (size_t)d * ET_STRIDE);
            acc[0][0] += a.x * bb.x; acc[0][1] += a.x * bb.y; acc[0][2] += a.x * bb.z; acc[0][3] += a.x * bb.w;
            acc[1][0] += a.y * bb.x; acc[1][1] += a.y * bb.y; acc[1][2] += a.y * bb.z; acc[1][3] += a.y * bb.w;
            acc[2][0] += a.z * bb.x; acc[2][1] += a.z * bb.y; acc[2][2] += a.z * bb.z; acc[2][3] += a.z * bb.w;
            acc[3][0] += a.w * bb.x; acc[3][1] += a.w * bb.y; acc[3][2] += a.w * bb.z; acc[3][3] += a.w * bb.w;
        }

        // reference-matching distance: fl(fl(a + b) - 2*c); 2c exact
#pragma unroll
        for (int j = 0; j < 4; ++j) {
            float as = arow[(tx << 2) + j];
#pragma unroll
            for (int k = 0; k < 4; ++k) {
                int c = (ty << 2) + k;
                float t1   = __fadd_rn(as, brow[c]);
                float dist = __fadd_rn(t1, -2.0f * acc[j][k]);
                if (dist < rmin[j]) { rmin[j] = dist; ridx[j] = c0 + c; }  // c ascending => ties keep lowest
            }
        }
    }
    __syncthreads();

    // cross-thread argmin reduction per row — LEXICOGRAPHIC (value, index)
    float* redv = et;                         // [16][128]
    int*   redi = (int*)(et + 16 * BR);       // [16][128]
#pragma unroll
    for (int j = 0; j < 4; ++j) {
        redv[ty * BR + (tx << 2) + j] = rmin[j];
        redi[ty * BR + (tx << 2) + j] = ridx[j];
    }
    __syncthreads();
    if (tid < BR) {
        int s = tid;
        float bv = redv[s]; int bi = redi[s];
#pragma unroll
        for (int t = 1; t < 16; ++t) {
            float v  = redv[t * BR + s];
            int   ii = redi[t * BR + s];
            if (v < bv || (v == bv && ii < bi)) { bv = v; bi = ii; }   // ties -> lowest code index (jnp.argmin)
        }
        sidx[s] = bi;
        if (p_idx) p_idx[n0 + s] = (float)bi;
        if (p_oh)  p_oh[(n0 + s) * (size_t)V + bi] = 1.0f;
        atomicAdd(&g_counts[bi], 1);
    }
    __syncthreads();

    // z_q gather (exact emb row — onehot@emb FFMA chain is exact), loss,
    // and z_q_st = fl(zp + fl(z_q - zp)). Coalesced emb reads + p_zq stores;
    // the zs read is 32-way-conflicted but this pass is ~0.4% of block time.
    float lp = 0.f;
    for (int i = tid; i < BR * D; i += NT) {
        int s = i >> 8, d = i & 255;
        float e   = emb[(size_t)sidx[s] * D + d];
        float zpv = zs[d * BR + s];
        float diff = __fadd_rn(e, -zpv);
        lp += diff * diff;
        if (p_zq) p_zq[(n0 + s) * (size_t)D + d] = __fadd_rn(zpv, diff);
    }

    // block loss reduction (reuse zs — all zs reads done)
    __syncthreads();
    zs[tid] = lp;
    __syncthreads();
    for (int st = NT / 2; st > 0; st >>= 1) {
        if (tid < st) zs[tid] += zs[tid + st];
        __syncthreads();
    }
    if (tid == 0) atomicAdd(&g_loss, (double)zs[0]);
}

// ---------------------------------------------------------------------------
// final: perplexity from counts, loss scalar
// ---------------------------------------------------------------------------
__global__ void vq_final(float* p_loss, float* p_ppl) {
    __shared__ float red[V];
    int c = threadIdx.x;
    float e = (float)g_counts[c] * (1.0f / 65536.0f);
    red[c] = e * logf(e + 1e-10f);
    __syncthreads();
    for (int st = 512; st > 0; st >>= 1) { if (c < st) red[c] += red[c + st]; __syncthreads(); }
    if (c == 0) {
        if (p_ppl)  *p_ppl  = expf(-red[0]);
        if (p_loss) *p_loss = (float)(1.25 * g_loss * (1.0 / 16777216.0));
    }
}

extern "C" void kernel_launch(void* const* d_in, const int* in_sizes, int n_in,
                              void* d_out, int out_size) {
    const float* z   = (const float*)d_in[0];
    const float* emb = (const float*)d_in[1];
    if (n_in >= 2 && in_sizes[0] == V * D && in_sizes[1] == NROWS * D) {
        z   = (const float*)d_in[1];
        emb = (const float*)d_in[0];
    }

    float* out = (float*)d_out;
    float *p_loss = nullptr, *p_zq = nullptr, *p_ppl = nullptr, *p_oh = nullptr, *p_idx = nullptr;
    const long long ZQ = (long long)NROWS * D;     // 16777216
    const long long OH = (long long)NROWS * V;     // 67108864
    const long long TOTAL = 1 + ZQ + 1 + OH + NROWS;  // 83951618
    long long osz = (long long)out_size;

    if (osz >= TOTAL) {                       // full 5-tuple concat
        p_loss = out;
        p_zq   = out + 1;
        p_ppl  = out + 1 + ZQ;
        p_oh   = p_ppl + 1;
        p_idx  = p_oh + OH;
    } else if (osz == ZQ)        p_zq  = out;
    else if (osz == OH)          p_oh  = out;
    else if (osz == NROWS)       p_idx = out;
    else if (osz == 1)           p_loss = out;
    else if (osz == 2)           { p_loss = out; p_ppl = out + 1; }
    else if (osz == ZQ + 1)      { p_loss = out; p_zq = out + 1; }
    else if (osz == ZQ + 2)      { p_loss = out; p_zq = out + 1; p_ppl = out + 1 + ZQ; }

    size_t smem = (size_t)(D * BR + D * ET_STRIDE + BR + BC) * sizeof(float) + BR * sizeof(int);
    cudaFuncSetAttribute(vq_main, cudaFuncAttributeMaxDynamicSharedMemorySize, (int)smem);

    vq_init<<<32, 32>>>(emb);
    vq_main<<<NROWS / BR, NT, smem>>>(z, emb, p_zq, p_oh, p_idx);
    vq_final<<<1, V>>>(p_loss, p_ppl);
}